// round 5
// baseline (speedup 1.0000x reference)
#include <cuda_runtime.h>
#include <math.h>

#define BATCH 8
#define QN 2048
#define KN 2048
#define DIN 1024
#define DPROJ 1024

// Scratch for projected Q/K/V (allocation-free: __device__ globals)
__device__ float g_pq[(size_t)BATCH * QN * DPROJ];
__device__ float g_pk[(size_t)BATCH * KN * DPROJ];
__device__ float g_pv[(size_t)BATCH * KN * DPROJ];

// ---------------------------------------------------------------------------
// NT GEMM: C[m,n] = scale * sum_k A[m,k] * Bm[n,k]  (+ bias[n])
// BM=BN=128, BK=16, 256 threads, 8x8 per-thread tile.
// ---------------------------------------------------------------------------
template <bool HAS_BIAS>
__global__ __launch_bounds__(256) void gemm_nt(
    const float* __restrict__ A, const float* __restrict__ Bm,
    const float* __restrict__ bias, float* __restrict__ C,
    int M, int N, int K, float scale,
    long aStride, long bStride, long cStride)
{
    const int BK = 16;
    __shared__ float As[BK][128];
    __shared__ float Bs[BK][128];

    const int bm = blockIdx.y * 128;
    const int bn = blockIdx.x * 128;
    const long bz = blockIdx.z;
    A  += bz * aStride;
    Bm += bz * bStride;
    C  += bz * cStride;

    const int tid = threadIdx.x;
    const int tx = tid & 15;   // 16 cols of threads -> 128 N
    const int ty = tid >> 4;   // 16 rows of threads -> 128 M

    float acc[8][8];
#pragma unroll
    for (int i = 0; i < 8; i++)
#pragma unroll
        for (int j = 0; j < 8; j++) acc[i][j] = 0.f;

    for (int k0 = 0; k0 < K; k0 += BK) {
        // Load A tile 128x16 (512 float4s / 256 threads = 2 each), transpose to As[k][m]
#pragma unroll
        for (int i = 0; i < 2; i++) {
            int idx = tid + i * 256;
            int row = idx >> 2;            // 4 float4 per row (16 floats)
            int kk  = (idx & 3) * 4;
            float4 v = *(const float4*)&A[(long)(bm + row) * K + k0 + kk];
            As[kk + 0][row] = v.x; As[kk + 1][row] = v.y;
            As[kk + 2][row] = v.z; As[kk + 3][row] = v.w;
        }
        // Load B tile 128x16 -> Bs[k][n]
#pragma unroll
        for (int i = 0; i < 2; i++) {
            int idx = tid + i * 256;
            int row = idx >> 2;
            int kk  = (idx & 3) * 4;
            float4 v = *(const float4*)&Bm[(long)(bn + row) * K + k0 + kk];
            Bs[kk + 0][row] = v.x; Bs[kk + 1][row] = v.y;
            Bs[kk + 2][row] = v.z; Bs[kk + 3][row] = v.w;
        }
        __syncthreads();

#pragma unroll
        for (int k = 0; k < BK; k++) {
            float4 a0 = *(const float4*)&As[k][ty * 8];
            float4 a1 = *(const float4*)&As[k][ty * 8 + 4];
            float4 b0 = *(const float4*)&Bs[k][tx * 8];
            float4 b1 = *(const float4*)&Bs[k][tx * 8 + 4];
            float ra[8] = {a0.x, a0.y, a0.z, a0.w, a1.x, a1.y, a1.z, a1.w};
            float rb[8] = {b0.x, b0.y, b0.z, b0.w, b1.x, b1.y, b1.z, b1.w};
#pragma unroll
            for (int i = 0; i < 8; i++)
#pragma unroll
                for (int j = 0; j < 8; j++) acc[i][j] = fmaf(ra[i], rb[j], acc[i][j]);
        }
        __syncthreads();
    }

#pragma unroll
    for (int i = 0; i < 8; i++) {
        int m = bm + ty * 8 + i;
#pragma unroll
        for (int j = 0; j < 8; j += 4) {
            int n = bn + tx * 8 + j;
            float4 v;
            v.x = acc[i][j + 0] * scale;
            v.y = acc[i][j + 1] * scale;
            v.z = acc[i][j + 2] * scale;
            v.w = acc[i][j + 3] * scale;
            if (HAS_BIAS) {
                v.x += bias[n + 0]; v.y += bias[n + 1];
                v.z += bias[n + 2]; v.w += bias[n + 3];
            }
            *(float4*)&C[(long)m * N + n] = v;
        }
    }
}

// ---------------------------------------------------------------------------
// NN GEMM: C[m,n] = sum_k A[m,k] * Bm[k,n]     (ctx = attn @ pv)
// ---------------------------------------------------------------------------
__global__ __launch_bounds__(256) void gemm_nn(
    const float* __restrict__ A, const float* __restrict__ Bm,
    float* __restrict__ C, int M, int N, int K,
    long aStride, long bStride, long cStride)
{
    const int BK = 16;
    __shared__ float As[BK][128];
    __shared__ float Bs[BK][128];

    const int bm = blockIdx.y * 128;
    const int bn = blockIdx.x * 128;
    const long bz = blockIdx.z;
    A  += bz * aStride;
    Bm += bz * bStride;
    C  += bz * cStride;

    const int tid = threadIdx.x;
    const int tx = tid & 15;
    const int ty = tid >> 4;

    float acc[8][8];
#pragma unroll
    for (int i = 0; i < 8; i++)
#pragma unroll
        for (int j = 0; j < 8; j++) acc[i][j] = 0.f;

    for (int k0 = 0; k0 < K; k0 += BK) {
        // A tile: rows m, cols k (contiguous) -> transpose into As[k][m]
#pragma unroll
        for (int i = 0; i < 2; i++) {
            int idx = tid + i * 256;
            int row = idx >> 2;
            int kk  = (idx & 3) * 4;
            float4 v = *(const float4*)&A[(long)(bm + row) * K + k0 + kk];
            As[kk + 0][row] = v.x; As[kk + 1][row] = v.y;
            As[kk + 2][row] = v.z; As[kk + 3][row] = v.w;
        }
        // B tile: rows k (16), cols n (128, contiguous) -> Bs[k][n]
#pragma unroll
        for (int i = 0; i < 2; i++) {
            int idx = tid + i * 256;
            int row = idx >> 5;            // 32 float4 per row of 128 floats
            int nn  = (idx & 31) * 4;
            float4 v = *(const float4*)&Bm[(long)(k0 + row) * N + bn + nn];
            *(float4*)&Bs[row][nn] = v;
        }
        __syncthreads();

#pragma unroll
        for (int k = 0; k < BK; k++) {
            float4 a0 = *(const float4*)&As[k][ty * 8];
            float4 a1 = *(const float4*)&As[k][ty * 8 + 4];
            float4 b0 = *(const float4*)&Bs[k][tx * 8];
            float4 b1 = *(const float4*)&Bs[k][tx * 8 + 4];
            float ra[8] = {a0.x, a0.y, a0.z, a0.w, a1.x, a1.y, a1.z, a1.w};
            float rb[8] = {b0.x, b0.y, b0.z, b0.w, b1.x, b1.y, b1.z, b1.w};
#pragma unroll
            for (int i = 0; i < 8; i++)
#pragma unroll
                for (int j = 0; j < 8; j++) acc[i][j] = fmaf(ra[i], rb[j], acc[i][j]);
        }
        __syncthreads();
    }

#pragma unroll
    for (int i = 0; i < 8; i++) {
        int m = bm + ty * 8 + i;
#pragma unroll
        for (int j = 0; j < 8; j += 4) {
            int n = bn + tx * 8 + j;
            float4 v = {acc[i][j], acc[i][j + 1], acc[i][j + 2], acc[i][j + 3]};
            *(float4*)&C[(long)m * N + n] = v;
        }
    }
}

// ---------------------------------------------------------------------------
// Row softmax with mask: one block per (b,q) row of 2048 scores.
// Masked entries: contribute nothing to max/sum, output exact 0
// (matches reference -1e9 + softmax + *mask to fp32 exactness:
// exp(-1e9 - max) underflows to 0 in fp32).
// ---------------------------------------------------------------------------
__global__ __launch_bounds__(256) void softmax_mask(
    float* __restrict__ S, const int* __restrict__ mask)
{
    const int row = blockIdx.x;          // b*QN + q
    const int b = row / QN;
    float* sp = S + (long)row * KN;
    const int* mp = mask + (long)b * KN;

    const int tid = threadIdx.x;
    __shared__ float red[32];

    float vals[8];
    int ms[8];
    float lmax = -INFINITY;
#pragma unroll
    for (int i = 0; i < 8; i++) {
        int k = tid + i * 256;
        vals[i] = sp[k];
        ms[i] = mp[k];
        if (ms[i]) lmax = fmaxf(lmax, vals[i]);
    }
    // block max
#pragma unroll
    for (int o = 16; o > 0; o >>= 1)
        lmax = fmaxf(lmax, __shfl_xor_sync(0xffffffffu, lmax, o));
    if ((tid & 31) == 0) red[tid >> 5] = lmax;
    __syncthreads();
    float rmax = (tid < 8) ? red[tid] : -INFINITY;
#pragma unroll
    for (int o = 4; o > 0; o >>= 1)
        rmax = fmaxf(rmax, __shfl_xor_sync(0xffffffffu, rmax, o));
    if (tid == 0) red[0] = rmax;
    __syncthreads();
    rmax = red[0];

    float lsum = 0.f;
#pragma unroll
    for (int i = 0; i < 8; i++) {
        vals[i] = ms[i] ? __expf(vals[i] - rmax) : 0.f;
        lsum += vals[i];
    }
#pragma unroll
    for (int o = 16; o > 0; o >>= 1)
        lsum += __shfl_xor_sync(0xffffffffu, lsum, o);
    __syncthreads();
    if ((tid & 31) == 0) red[tid >> 5] = lsum;
    __syncthreads();
    float rsum = (tid < 8) ? red[tid] : 0.f;
#pragma unroll
    for (int o = 4; o > 0; o >>= 1)
        rsum += __shfl_xor_sync(0xffffffffu, rsum, o);
    if (tid == 0) red[0] = rsum;
    __syncthreads();
    rsum = red[0];

    float inv = (rsum > 0.f) ? (1.f / rsum) : 0.f;
#pragma unroll
    for (int i = 0; i < 8; i++) {
        int k = tid + i * 256;
        sp[k] = vals[i] * inv;
    }
}

// ---------------------------------------------------------------------------
// kernel_launch
// Inputs: query, key, value, mask, Wq, bq, Wk, bk, Wv, bv
// Output: [ctx (B*QN*DPROJ) | attn (B*QN*KN)]
// ---------------------------------------------------------------------------
extern "C" void kernel_launch(void* const* d_in, const int* in_sizes, int n_in,
                              void* d_out, int out_size)
{
    const float* query = (const float*)d_in[0];
    const float* key   = (const float*)d_in[1];
    const float* value = (const float*)d_in[2];
    const int*   mask  = (const int*)d_in[3];
    const float* Wq    = (const float*)d_in[4];
    const float* bq    = (const float*)d_in[5];
    const float* Wk    = (const float*)d_in[6];
    const float* bk    = (const float*)d_in[7];
    const float* Wv    = (const float*)d_in[8];
    const float* bv    = (const float*)d_in[9];

    float* ctx  = (float*)d_out;
    float* attn = (float*)d_out + (size_t)BATCH * QN * DPROJ;

    float *pq, *pk, *pv;
    cudaGetSymbolAddress((void**)&pq, g_pq);
    cudaGetSymbolAddress((void**)&pk, g_pk);
    cudaGetSymbolAddress((void**)&pv, g_pv);

    dim3 blk(256);

    // Projections: [B*QN, DIN] x [DPROJ, DIN]^T + bias  (all batches fused)
    {
        dim3 grid(DPROJ / 128, (BATCH * QN) / 128, 1);
        gemm_nt<true><<<grid, blk>>>(query, Wq, bq, pq, BATCH * QN, DPROJ, DIN, 1.f, 0, 0, 0);
        gemm_nt<true><<<grid, blk>>>(key,   Wk, bk, pk, BATCH * KN, DPROJ, DIN, 1.f, 0, 0, 0);
        gemm_nt<true><<<grid, blk>>>(value, Wv, bv, pv, BATCH * KN, DPROJ, DIN, 1.f, 0, 0, 0);
    }

    // Scores: per batch, [QN, DPROJ] x [KN, DPROJ]^T * (1/32) -> attn region
    {
        dim3 grid(KN / 128, QN / 128, BATCH);
        gemm_nt<false><<<grid, blk>>>(pq, pk, nullptr, attn, QN, KN, DPROJ,
                                      0.03125f,
                                      (long)QN * DPROJ, (long)KN * DPROJ, (long)QN * KN);
    }

    // Masked softmax in-place over attn rows
    softmax_mask<<<BATCH * QN, 256>>>(attn, mask);

    // ctx = attn @ pv : per batch [QN, KN] x [KN, DPROJ]
    {
        dim3 grid(DPROJ / 128, QN / 128, BATCH);
        gemm_nn<<<grid, blk>>>(attn, pv, ctx, QN, DPROJ, KN,
                               (long)QN * KN, (long)KN * DPROJ, (long)QN * DPROJ);
    }
}

// round 7
// speedup vs baseline: 2.7298x; 2.7298x over previous
#include <cuda_runtime.h>
#include <math.h>
#include <stdint.h>

#define BATCH 8
#define QN 2048
#define KN 2048
#define DIN 1024
#define DPROJ 1024

// Scratch for projected Q/K/V (allocation-free: __device__ globals)
__device__ float g_pq[(size_t)BATCH * QN * DPROJ];
__device__ float g_pk[(size_t)BATCH * KN * DPROJ];
__device__ float g_pv[(size_t)BATCH * KN * DPROJ];

// ---------------------------------------------------------------------------
// fp32 -> tf32 with round-to-nearest (avoids truncation bias)
// ---------------------------------------------------------------------------
__device__ __forceinline__ uint32_t f2tf32(float f) {
    uint32_t u;
    asm("cvt.rna.tf32.f32 %0, %1;" : "=r"(u) : "f"(f));
    return u;
}

__device__ __forceinline__ void mma_tf32(float* d, const uint32_t* a, const uint32_t* b) {
    asm volatile(
        "mma.sync.aligned.m16n8k8.row.col.f32.tf32.tf32.f32 "
        "{%0,%1,%2,%3}, {%4,%5,%6,%7}, {%8,%9}, {%0,%1,%2,%3};\n"
        : "+f"(d[0]), "+f"(d[1]), "+f"(d[2]), "+f"(d[3])
        : "r"(a[0]), "r"(a[1]), "r"(a[2]), "r"(a[3]),
          "r"(b[0]), "r"(b[1]));
}

// ---------------------------------------------------------------------------
// Tensor-core GEMM, tf32 inputs / fp32 accumulate.
// MODE 0 (NT): C[m,n] = scale*sum_k A[m,k]*Bm[n,k] (+bias[n])
// MODE 1 (NN): C[m,n] = scale*sum_k A[m,k]*Bm[k,n]
// Block tile 128x128, BK=16, 256 threads (8 warps, 2x4), warp tile 64x32.
// Double-buffered smem, register-staged global loads, cvt-to-tf32 at STS.
// All dims assumed multiples of tile sizes (true for this problem).
// ---------------------------------------------------------------------------
template <int MODE, bool HAS_BIAS>
__global__ __launch_bounds__(256) void gemm_tc(
    const float* __restrict__ A, const float* __restrict__ Bm,
    const float* __restrict__ bias, float* __restrict__ C,
    int N, int K, float scale,
    long aStride, long bStride, long cStride)
{
    constexpr int BK = 16;
    constexpr int BROWS = MODE ? BK : 128;
    constexpr int BSTRD = MODE ? 136 : 20;   // pads chosen for conflict-free frag reads

    __shared__ uint32_t As[2][128][20];
    __shared__ uint32_t Bs[2][BROWS][BSTRD];

    const int bm = blockIdx.y * 128;
    const int bn = blockIdx.x * 128;
    const long bz = blockIdx.z;
    A  += bz * aStride;
    Bm += bz * bStride;
    C  += bz * cStride;

    const int tid  = threadIdx.x;
    const int lane = tid & 31;
    const int wid  = tid >> 5;
    const int wm   = (wid & 1) * 64;   // warp m-origin within block
    const int wn   = (wid >> 1) * 32;  // warp n-origin within block
    const int lr   = lane >> 2;        // 0..7
    const int lc   = lane & 3;         // 0..3

    // global-load coordinates: 512 float4s per 128x16 tile / 256 threads = 2 each
    const int g_row = tid >> 2;        // 0..63 (second load at +64)
    const int g_kc  = (tid & 3) * 4;   // 0,4,8,12
    const int g_kr  = tid >> 5;        // 0..7 (NN B tile, second load at +8)
    const int g_nc  = (tid & 31) * 4;  // 0..124 (NN B tile)

    float acc[4][4][4];
#pragma unroll
    for (int i = 0; i < 4; i++)
#pragma unroll
        for (int j = 0; j < 4; j++)
#pragma unroll
            for (int q = 0; q < 4; q++) acc[i][j][q] = 0.f;

    const int tiles = K / BK;
    float4 ra0, ra1, rb0, rb1;

    auto ldg_tile = [&](int t) {
        const long k0 = (long)t * BK;
        ra0 = *(const float4*)&A[(long)(bm + g_row) * K + k0 + g_kc];
        ra1 = *(const float4*)&A[(long)(bm + g_row + 64) * K + k0 + g_kc];
        if (MODE == 0) {
            rb0 = *(const float4*)&Bm[(long)(bn + g_row) * K + k0 + g_kc];
            rb1 = *(const float4*)&Bm[(long)(bn + g_row + 64) * K + k0 + g_kc];
        } else {
            rb0 = *(const float4*)&Bm[(k0 + g_kr) * (long)N + bn + g_nc];
            rb1 = *(const float4*)&Bm[(k0 + g_kr + 8) * (long)N + bn + g_nc];
        }
    };

    auto sts_tile = [&](int b) {
        As[b][g_row][g_kc + 0] = f2tf32(ra0.x);
        As[b][g_row][g_kc + 1] = f2tf32(ra0.y);
        As[b][g_row][g_kc + 2] = f2tf32(ra0.z);
        As[b][g_row][g_kc + 3] = f2tf32(ra0.w);
        As[b][g_row + 64][g_kc + 0] = f2tf32(ra1.x);
        As[b][g_row + 64][g_kc + 1] = f2tf32(ra1.y);
        As[b][g_row + 64][g_kc + 2] = f2tf32(ra1.z);
        As[b][g_row + 64][g_kc + 3] = f2tf32(ra1.w);
        if (MODE == 0) {
            Bs[b][g_row][g_kc + 0] = f2tf32(rb0.x);
            Bs[b][g_row][g_kc + 1] = f2tf32(rb0.y);
            Bs[b][g_row][g_kc + 2] = f2tf32(rb0.z);
            Bs[b][g_row][g_kc + 3] = f2tf32(rb0.w);
            Bs[b][g_row + 64][g_kc + 0] = f2tf32(rb1.x);
            Bs[b][g_row + 64][g_kc + 1] = f2tf32(rb1.y);
            Bs[b][g_row + 64][g_kc + 2] = f2tf32(rb1.z);
            Bs[b][g_row + 64][g_kc + 3] = f2tf32(rb1.w);
        } else {
            Bs[b][g_kr][g_nc + 0] = f2tf32(rb0.x);
            Bs[b][g_kr][g_nc + 1] = f2tf32(rb0.y);
            Bs[b][g_kr][g_nc + 2] = f2tf32(rb0.z);
            Bs[b][g_kr][g_nc + 3] = f2tf32(rb0.w);
            Bs[b][g_kr + 8][g_nc + 0] = f2tf32(rb1.x);
            Bs[b][g_kr + 8][g_nc + 1] = f2tf32(rb1.y);
            Bs[b][g_kr + 8][g_nc + 2] = f2tf32(rb1.z);
            Bs[b][g_kr + 8][g_nc + 3] = f2tf32(rb1.w);
        }
    };

    auto compute = [&](int b) {
#pragma unroll
        for (int kk = 0; kk < BK; kk += 8) {
            uint32_t af[4][4], bf[4][2];
#pragma unroll
            for (int fm = 0; fm < 4; fm++) {
                const int m = wm + fm * 16;
                af[fm][0] = As[b][m + lr][kk + lc];
                af[fm][1] = As[b][m + 8 + lr][kk + lc];
                af[fm][2] = As[b][m + lr][kk + 4 + lc];
                af[fm][3] = As[b][m + 8 + lr][kk + 4 + lc];
            }
#pragma unroll
            for (int fn = 0; fn < 4; fn++) {
                const int n = wn + fn * 8 + lr;
                if (MODE == 0) {
                    bf[fn][0] = Bs[b][n][kk + lc];
                    bf[fn][1] = Bs[b][n][kk + 4 + lc];
                } else {
                    bf[fn][0] = Bs[b][kk + lc][n];
                    bf[fn][1] = Bs[b][kk + 4 + lc][n];
                }
            }
#pragma unroll
            for (int fm = 0; fm < 4; fm++)
#pragma unroll
                for (int fn = 0; fn < 4; fn++)
                    mma_tf32(acc[fm][fn], af[fm], bf[fn]);
        }
    };

    // Prologue
    ldg_tile(0);
    sts_tile(0);
    __syncthreads();

    int buf = 0;
    for (int t = 0; t < tiles; t++) {
        const bool has_next = (t + 1 < tiles);
        if (has_next) ldg_tile(t + 1);
        compute(buf);
        if (has_next) {
            __syncthreads();          // all warps done reading buf^1 (iter t-1)
            sts_tile(buf ^ 1);
            buf ^= 1;
            __syncthreads();          // new tile visible
        }
    }

    // Epilogue: c0,c1 at (r, c..c+1); c2,c3 at (r+8, c..c+1)
#pragma unroll
    for (int fm = 0; fm < 4; fm++) {
        const int r = bm + wm + fm * 16 + lr;
#pragma unroll
        for (int fn = 0; fn < 4; fn++) {
            const int c = bn + wn + fn * 8 + lc * 2;
            float bx = 0.f, by = 0.f;
            if (HAS_BIAS) { bx = bias[c]; by = bias[c + 1]; }
            float2 v0, v1;
            v0.x = acc[fm][fn][0] * scale + bx;
            v0.y = acc[fm][fn][1] * scale + by;
            v1.x = acc[fm][fn][2] * scale + bx;
            v1.y = acc[fm][fn][3] * scale + by;
            *(float2*)&C[(long)r * N + c] = v0;
            *(float2*)&C[(long)(r + 8) * N + c] = v1;
        }
    }
}

// ---------------------------------------------------------------------------
// Row softmax with mask: one block per (b,q) row of 2048 scores.
// Masked entries contribute nothing and output exact 0 (matches reference
// -1e9 + softmax + *mask to fp32 exactness).
// ---------------------------------------------------------------------------
__global__ __launch_bounds__(256) void softmax_mask(
    float* __restrict__ S, const int* __restrict__ mask)
{
    const int row = blockIdx.x;          // b*QN + q
    const int b = row / QN;
    float* sp = S + (long)row * KN;
    const int* mp = mask + (long)b * KN;

    const int tid = threadIdx.x;
    __shared__ float red[32];

    float vals[8];
    int ms[8];
    float lmax = -INFINITY;
#pragma unroll
    for (int i = 0; i < 8; i++) {
        int k = tid + i * 256;
        vals[i] = sp[k];
        ms[i] = mp[k];
        if (ms[i]) lmax = fmaxf(lmax, vals[i]);
    }
#pragma unroll
    for (int o = 16; o > 0; o >>= 1)
        lmax = fmaxf(lmax, __shfl_xor_sync(0xffffffffu, lmax, o));
    if ((tid & 31) == 0) red[tid >> 5] = lmax;
    __syncthreads();
    float rmax = (tid < 8) ? red[tid] : -INFINITY;
#pragma unroll
    for (int o = 4; o > 0; o >>= 1)
        rmax = fmaxf(rmax, __shfl_xor_sync(0xffffffffu, rmax, o));
    if (tid == 0) red[0] = rmax;
    __syncthreads();
    rmax = red[0];

    float lsum = 0.f;
#pragma unroll
    for (int i = 0; i < 8; i++) {
        vals[i] = ms[i] ? __expf(vals[i] - rmax) : 0.f;
        lsum += vals[i];
    }
#pragma unroll
    for (int o = 16; o > 0; o >>= 1)
        lsum += __shfl_xor_sync(0xffffffffu, lsum, o);
    __syncthreads();
    if ((tid & 31) == 0) red[tid >> 5] = lsum;
    __syncthreads();
    float rsum = (tid < 8) ? red[tid] : 0.f;
#pragma unroll
    for (int o = 4; o > 0; o >>= 1)
        rsum += __shfl_xor_sync(0xffffffffu, rsum, o);
    if (tid == 0) red[0] = rsum;
    __syncthreads();
    rsum = red[0];

    float inv = (rsum > 0.f) ? (1.f / rsum) : 0.f;
#pragma unroll
    for (int i = 0; i < 8; i++) {
        int k = tid + i * 256;
        sp[k] = vals[i] * inv;
    }
}

// ---------------------------------------------------------------------------
// kernel_launch
// Inputs: query, key, value, mask, Wq, bq, Wk, bk, Wv, bv
// Output: [ctx (B*QN*DPROJ) | attn (B*QN*KN)]
// ---------------------------------------------------------------------------
extern "C" void kernel_launch(void* const* d_in, const int* in_sizes, int n_in,
                              void* d_out, int out_size)
{
    const float* query = (const float*)d_in[0];
    const float* key   = (const float*)d_in[1];
    const float* value = (const float*)d_in[2];
    const int*   mask  = (const int*)d_in[3];
    const float* Wq    = (const float*)d_in[4];
    const float* bq    = (const float*)d_in[5];
    const float* Wk    = (const float*)d_in[6];
    const float* bk    = (const float*)d_in[7];
    const float* Wv    = (const float*)d_in[8];
    const float* bv    = (const float*)d_in[9];

    float* ctx  = (float*)d_out;
    float* attn = (float*)d_out + (size_t)BATCH * QN * DPROJ;

    float *pq, *pk, *pv;
    cudaGetSymbolAddress((void**)&pq, g_pq);
    cudaGetSymbolAddress((void**)&pk, g_pk);
    cudaGetSymbolAddress((void**)&pv, g_pv);

    dim3 blk(256);

    // Projections: [B*QN, DIN] x [DPROJ, DIN]^T + bias  (all batches fused)
    {
        dim3 grid(DPROJ / 128, (BATCH * QN) / 128, 1);
        gemm_tc<0, true><<<grid, blk>>>(query, Wq, bq, pq, DPROJ, DIN, 1.f, 0, 0, 0);
        gemm_tc<0, true><<<grid, blk>>>(key,   Wk, bk, pk, DPROJ, DIN, 1.f, 0, 0, 0);
        gemm_tc<0, true><<<grid, blk>>>(value, Wv, bv, pv, DPROJ, DIN, 1.f, 0, 0, 0);
    }

    // Scores: per batch, [QN, DPROJ] x [KN, DPROJ]^T * (1/32) -> attn region
    {
        dim3 grid(KN / 128, QN / 128, BATCH);
        gemm_tc<0, false><<<grid, blk>>>(pq, pk, nullptr, attn, KN, DPROJ,
                                         0.03125f,
                                         (long)QN * DPROJ, (long)KN * DPROJ, (long)QN * KN);
    }

    // Masked softmax in-place over attn rows
    softmax_mask<<<BATCH * QN, 256>>>(attn, mask);

    // ctx = attn @ pv : per batch [QN, KN] x [KN, DPROJ]
    {
        dim3 grid(DPROJ / 128, QN / 128, BATCH);
        gemm_tc<1, false><<<grid, blk>>>(attn, pv, nullptr, ctx, DPROJ, KN,
                                         1.f,
                                         (long)QN * KN, (long)KN * DPROJ, (long)QN * DPROJ);
    }
}

// round 8
// speedup vs baseline: 3.0662x; 1.1232x over previous
#include <cuda_runtime.h>
#include <math.h>
#include <stdint.h>

#define BATCH 8
#define QN 2048
#define KN 2048
#define DIN 1024
#define DPROJ 1024

// Scratch: pq, pk in [tokens][d]; pv stored TRANSPOSED [d][tokens] per batch
__device__ float g_pq[(size_t)BATCH * QN * DPROJ];
__device__ float g_pk[(size_t)BATCH * KN * DPROJ];
__device__ float g_pvT[(size_t)BATCH * DPROJ * KN];

// ---------------------------------------------------------------------------
// fp32 -> tf32 round-to-nearest
// ---------------------------------------------------------------------------
__device__ __forceinline__ uint32_t f2tf32(float f) {
    uint32_t u;
    asm("cvt.rna.tf32.f32 %0, %1;" : "=r"(u) : "f"(f));
    return u;
}

__device__ __forceinline__ void mma_tf32(float* d, const uint32_t* a, const uint32_t* b) {
    asm volatile(
        "mma.sync.aligned.m16n8k8.row.col.f32.tf32.tf32.f32 "
        "{%0,%1,%2,%3}, {%4,%5,%6,%7}, {%8,%9}, {%0,%1,%2,%3};\n"
        : "+f"(d[0]), "+f"(d[1]), "+f"(d[2]), "+f"(d[3])
        : "r"(a[0]), "r"(a[1]), "r"(a[2]), "r"(a[3]),
          "r"(b[0]), "r"(b[1]));
}

// ldmatrix x4 on 32-bit data: each "8x8 b16" matrix = 8x4 float tile;
// output lane->(row=lane>>2, col=lane&3) == tf32 mma fragment layout.
__device__ __forceinline__ void ldsm4(uint32_t& r0, uint32_t& r1,
                                      uint32_t& r2, uint32_t& r3, uint32_t addr) {
    asm volatile("ldmatrix.sync.aligned.m8n8.x4.shared.b16 {%0,%1,%2,%3}, [%4];"
        : "=r"(r0), "=r"(r1), "=r"(r2), "=r"(r3) : "r"(addr));
}

// ---------------------------------------------------------------------------
// NT tensor-core GEMM, tf32/fp32-acc: C[m,n] = scale*sum_k A[m,k]*Bm[n,k] (+bias)
// BIAS: 0 none, 1 col (bias[n]), 2 row (bias[m])
// Block 128x128, BK=16, 8 warps (2x4), warp tile 64x32, double-buffered smem,
// register-staged LDG, tf32 conversion at STS.128, fragments via ldmatrix.
// ---------------------------------------------------------------------------
template <int BIAS>
__global__ __launch_bounds__(256) void gemm_tc(
    const float* __restrict__ A, const float* __restrict__ Bm,
    const float* __restrict__ bias, float* __restrict__ C,
    int N, int K, float scale,
    long aStride, long bStride, long cStride)
{
    constexpr int BK = 16;
    constexpr int STRD = 20;   // pad: row stride 20 words -> conflict-free LDSM

    __shared__ uint32_t As[2][128][STRD];
    __shared__ uint32_t Bs[2][128][STRD];

    const int bm = blockIdx.y * 128;
    const int bn = blockIdx.x * 128;
    const long bz = blockIdx.z;
    A  += bz * aStride;
    Bm += bz * bStride;
    C  += bz * cStride;

    const int tid  = threadIdx.x;
    const int lane = tid & 31;
    const int wid  = tid >> 5;
    const int wm   = (wid & 1) * 64;
    const int wn   = (wid >> 1) * 32;
    const int lr   = lane >> 2;
    const int lc   = lane & 3;

    // LDG coords: 128x16 tile = 512 float4 / 256 thr = 2 each
    const int g_row = tid >> 2;
    const int g_kc  = (tid & 3) * 4;

    // ldmatrix per-lane offsets (matrix id mi = lane>>3)
    const int mi = lane >> 3;
    const int aRow = (lane & 7) + (mi & 1) * 8;   // A: r0..r3 = (m,kk),(m+8,kk),(m,kk+4),(m+8,kk+4)
    const int aCol = (mi >> 1) * 4;
    const int bRow = (lane & 7) + (mi >> 1) * 8;  // B: r0,r1 = fn(n..n+7) b0,b1; r2,r3 = fn+1
    const int bCol = (mi & 1) * 4;

    const uint32_t asb0 = (uint32_t)__cvta_generic_to_shared(&As[0][0][0]);
    const uint32_t bsb0 = (uint32_t)__cvta_generic_to_shared(&Bs[0][0][0]);
    const uint32_t aLane = (uint32_t)((aRow * STRD + aCol) * 4);
    const uint32_t bLane = (uint32_t)((bRow * STRD + bCol) * 4);
    const uint32_t bufBytes = 128 * STRD * 4;

    float acc[4][4][4];
#pragma unroll
    for (int i = 0; i < 4; i++)
#pragma unroll
        for (int j = 0; j < 4; j++)
#pragma unroll
            for (int q = 0; q < 4; q++) acc[i][j][q] = 0.f;

    const int tiles = K / BK;
    float4 ra0, ra1, rb0, rb1;

    auto ldg_tile = [&](int t) {
        const long k0 = (long)t * BK;
        ra0 = *(const float4*)&A[(long)(bm + g_row) * K + k0 + g_kc];
        ra1 = *(const float4*)&A[(long)(bm + g_row + 64) * K + k0 + g_kc];
        rb0 = *(const float4*)&Bm[(long)(bn + g_row) * K + k0 + g_kc];
        rb1 = *(const float4*)&Bm[(long)(bn + g_row + 64) * K + k0 + g_kc];
    };

    auto sts_tile = [&](int b) {
        *(uint4*)&As[b][g_row][g_kc] =
            make_uint4(f2tf32(ra0.x), f2tf32(ra0.y), f2tf32(ra0.z), f2tf32(ra0.w));
        *(uint4*)&As[b][g_row + 64][g_kc] =
            make_uint4(f2tf32(ra1.x), f2tf32(ra1.y), f2tf32(ra1.z), f2tf32(ra1.w));
        *(uint4*)&Bs[b][g_row][g_kc] =
            make_uint4(f2tf32(rb0.x), f2tf32(rb0.y), f2tf32(rb0.z), f2tf32(rb0.w));
        *(uint4*)&Bs[b][g_row + 64][g_kc] =
            make_uint4(f2tf32(rb1.x), f2tf32(rb1.y), f2tf32(rb1.z), f2tf32(rb1.w));
    };

    auto compute = [&](int b) {
        const uint32_t asA = asb0 + b * bufBytes + aLane;
        const uint32_t bsB = bsb0 + b * bufBytes + bLane;
#pragma unroll
        for (int kk = 0; kk < BK; kk += 8) {
            uint32_t af[4][4], bf[4][2];
#pragma unroll
            for (int fm = 0; fm < 4; fm++) {
                const int m = wm + fm * 16;
                ldsm4(af[fm][0], af[fm][1], af[fm][2], af[fm][3],
                      asA + (uint32_t)((m * STRD + kk) * 4));
            }
#pragma unroll
            for (int fp = 0; fp < 2; fp++) {
                const int n = wn + fp * 16;
                ldsm4(bf[2 * fp][0], bf[2 * fp][1], bf[2 * fp + 1][0], bf[2 * fp + 1][1],
                      bsB + (uint32_t)((n * STRD + kk) * 4));
            }
#pragma unroll
            for (int fm = 0; fm < 4; fm++)
#pragma unroll
                for (int fn = 0; fn < 4; fn++)
                    mma_tf32(acc[fm][fn], af[fm], bf[fn]);
        }
    };

    // Prologue
    ldg_tile(0);
    sts_tile(0);
    __syncthreads();

    int buf = 0;
    for (int t = 0; t < tiles; t++) {
        const bool has_next = (t + 1 < tiles);
        if (has_next) ldg_tile(t + 1);
        compute(buf);
        if (has_next) {
            __syncthreads();
            sts_tile(buf ^ 1);
            buf ^= 1;
            __syncthreads();
        }
    }

    // Epilogue: c0,c1 at (r, c..c+1); c2,c3 at (r+8, c..c+1)
#pragma unroll
    for (int fm = 0; fm < 4; fm++) {
        const int r = bm + wm + fm * 16 + lr;
        float br0 = 0.f, br1 = 0.f;
        if (BIAS == 2) { br0 = bias[r]; br1 = bias[r + 8]; }
#pragma unroll
        for (int fn = 0; fn < 4; fn++) {
            const int c = bn + wn + fn * 8 + lc * 2;
            float bc0 = 0.f, bc1 = 0.f;
            if (BIAS == 1) { bc0 = bias[c]; bc1 = bias[c + 1]; }
            float2 v0, v1;
            v0.x = acc[fm][fn][0] * scale + bc0 + br0;
            v0.y = acc[fm][fn][1] * scale + bc1 + br0;
            v1.x = acc[fm][fn][2] * scale + bc0 + br1;
            v1.y = acc[fm][fn][3] * scale + bc1 + br1;
            *(float2*)&C[(long)r * N + c] = v0;
            *(float2*)&C[(long)(r + 8) * N + c] = v1;
        }
    }
}

// ---------------------------------------------------------------------------
// Row softmax with mask: one block per (b,q) row of 2048 scores.
// Masked entries contribute nothing and output exact 0 (matches reference).
// ---------------------------------------------------------------------------
__global__ __launch_bounds__(256) void softmax_mask(
    float* __restrict__ S, const int* __restrict__ mask)
{
    const int row = blockIdx.x;
    const int b = row / QN;
    float* sp = S + (long)row * KN;
    const int* mp = mask + (long)b * KN;

    const int tid = threadIdx.x;
    __shared__ float red[32];

    float vals[8];
    int ms[8];
    float lmax = -INFINITY;
#pragma unroll
    for (int i = 0; i < 8; i++) {
        int k = tid + i * 256;
        vals[i] = sp[k];
        ms[i] = mp[k];
        if (ms[i]) lmax = fmaxf(lmax, vals[i]);
    }
#pragma unroll
    for (int o = 16; o > 0; o >>= 1)
        lmax = fmaxf(lmax, __shfl_xor_sync(0xffffffffu, lmax, o));
    if ((tid & 31) == 0) red[tid >> 5] = lmax;
    __syncthreads();
    float rmax = (tid < 8) ? red[tid] : -INFINITY;
#pragma unroll
    for (int o = 4; o > 0; o >>= 1)
        rmax = fmaxf(rmax, __shfl_xor_sync(0xffffffffu, rmax, o));
    if (tid == 0) red[0] = rmax;
    __syncthreads();
    rmax = red[0];

    float lsum = 0.f;
#pragma unroll
    for (int i = 0; i < 8; i++) {
        vals[i] = ms[i] ? __expf(vals[i] - rmax) : 0.f;
        lsum += vals[i];
    }
#pragma unroll
    for (int o = 16; o > 0; o >>= 1)
        lsum += __shfl_xor_sync(0xffffffffu, lsum, o);
    __syncthreads();
    if ((tid & 31) == 0) red[tid >> 5] = lsum;
    __syncthreads();
    float rsum = (tid < 8) ? red[tid] : 0.f;
#pragma unroll
    for (int o = 4; o > 0; o >>= 1)
        rsum += __shfl_xor_sync(0xffffffffu, rsum, o);
    if (tid == 0) red[0] = rsum;
    __syncthreads();
    rsum = red[0];

    float inv = (rsum > 0.f) ? (1.f / rsum) : 0.f;
#pragma unroll
    for (int i = 0; i < 8; i++) {
        int k = tid + i * 256;
        sp[k] = vals[i] * inv;
    }
}

// ---------------------------------------------------------------------------
// kernel_launch
// Inputs: query, key, value, mask, Wq, bq, Wk, bk, Wv, bv
// Output: [ctx (B*QN*DPROJ) | attn (B*QN*KN)]
// ---------------------------------------------------------------------------
extern "C" void kernel_launch(void* const* d_in, const int* in_sizes, int n_in,
                              void* d_out, int out_size)
{
    const float* query = (const float*)d_in[0];
    const float* key   = (const float*)d_in[1];
    const float* value = (const float*)d_in[2];
    const int*   mask  = (const int*)d_in[3];
    const float* Wq    = (const float*)d_in[4];
    const float* bq    = (const float*)d_in[5];
    const float* Wk    = (const float*)d_in[6];
    const float* bk    = (const float*)d_in[7];
    const float* Wv    = (const float*)d_in[8];
    const float* bv    = (const float*)d_in[9];

    float* ctx  = (float*)d_out;
    float* attn = (float*)d_out + (size_t)BATCH * QN * DPROJ;

    float *pq, *pk, *pvT;
    cudaGetSymbolAddress((void**)&pq, g_pq);
    cudaGetSymbolAddress((void**)&pk, g_pk);
    cudaGetSymbolAddress((void**)&pvT, g_pvT);

    dim3 blk(256);

    // Q/K projections: C[token, d] = query @ Wq^T + bq   (col-bias)
    {
        dim3 grid(DPROJ / 128, (BATCH * QN) / 128, 1);
        gemm_tc<1><<<grid, blk>>>(query, Wq, bq, pq, DPROJ, DIN, 1.f, 0, 0, 0);
        gemm_tc<1><<<grid, blk>>>(key,   Wk, bk, pk, DPROJ, DIN, 1.f, 0, 0, 0);
    }

    // V projection TRANSPOSED: pvT[d, token] = Wv @ value^T + bv[d]  (row-bias)
    {
        dim3 grid(KN / 128, DPROJ / 128, BATCH);
        gemm_tc<2><<<grid, blk>>>(Wv, value, bv, pvT, KN, DIN, 1.f,
                                  0, (long)KN * DIN, (long)DPROJ * KN);
    }

    // Scores: [QN, DPROJ] x [KN, DPROJ]^T * (1/32) -> attn region
    {
        dim3 grid(KN / 128, QN / 128, BATCH);
        gemm_tc<0><<<grid, blk>>>(pq, pk, nullptr, attn, KN, DPROJ,
                                  0.03125f,
                                  (long)QN * DPROJ, (long)KN * DPROJ, (long)QN * KN);
    }

    // Masked softmax in-place over attn rows
    softmax_mask<<<BATCH * QN, 256>>>(attn, mask);

    // ctx[q, d] = sum_k attn[q,k] * pvT[d,k]   (NT)
    {
        dim3 grid(DPROJ / 128, QN / 128, BATCH);
        gemm_tc<0><<<grid, blk>>>(attn, pvT, nullptr, ctx, DPROJ, KN,
                                  1.f,
                                  (long)QN * KN, (long)DPROJ * KN, (long)QN * DPROJ);
    }
}

// round 9
// speedup vs baseline: 3.2749x; 1.0681x over previous
#include <cuda_runtime.h>
#include <math.h>
#include <stdint.h>

#define BATCH 8
#define QN 2048
#define KN 2048
#define DIN 1024
#define DPROJ 1024

// Scratch: pq, pk in [tokens][d]; pv stored TRANSPOSED [d][tokens] per batch
__device__ float g_pq[(size_t)BATCH * QN * DPROJ];
__device__ float g_pk[(size_t)BATCH * KN * DPROJ];
__device__ float g_pvT[(size_t)BATCH * DPROJ * KN];

// ---------------------------------------------------------------------------
// fp32 -> tf32 round-to-nearest
// ---------------------------------------------------------------------------
__device__ __forceinline__ uint32_t f2tf32(float f) {
    uint32_t u;
    asm("cvt.rna.tf32.f32 %0, %1;" : "=r"(u) : "f"(f));
    return u;
}

__device__ __forceinline__ void mma_tf32(float* d, const uint32_t* a, const uint32_t* b) {
    asm volatile(
        "mma.sync.aligned.m16n8k8.row.col.f32.tf32.tf32.f32 "
        "{%0,%1,%2,%3}, {%4,%5,%6,%7}, {%8,%9}, {%0,%1,%2,%3};\n"
        : "+f"(d[0]), "+f"(d[1]), "+f"(d[2]), "+f"(d[3])
        : "r"(a[0]), "r"(a[1]), "r"(a[2]), "r"(a[3]),
          "r"(b[0]), "r"(b[1]));
}

// ldmatrix x4 on 32-bit data: each "8x8 b16" matrix = 8x4 float tile;
// output lane->(row=lane>>2, col=lane&3) == tf32 mma fragment layout.
__device__ __forceinline__ void ldsm4(uint32_t& r0, uint32_t& r1,
                                      uint32_t& r2, uint32_t& r3, uint32_t addr) {
    asm volatile("ldmatrix.sync.aligned.m8n8.x4.shared.b16 {%0,%1,%2,%3}, [%4];"
        : "=r"(r0), "=r"(r1), "=r"(r2), "=r"(r3) : "r"(addr));
}

// ---------------------------------------------------------------------------
// NT tensor-core GEMM, tf32/fp32-acc: C[m,n] = scale*sum_k A[m,k]*Bm[n,k] (+bias)
// BIAS: 0 none, 1 col (bias[n]), 2 row (bias[m])
// Block 128x128, BK=16, 4 warps (2x2), warp tile 64x64 (high smem reuse),
// double-buffered smem, register-staged LDG, tf32 at STS.128, ldmatrix frags.
// 128 threads/block -> 2 blocks/SM (regs ~210, smem 41KB).
// ---------------------------------------------------------------------------
template <int BIAS>
__global__ __launch_bounds__(128) void gemm_tc(
    const float* __restrict__ A, const float* __restrict__ Bm,
    const float* __restrict__ bias, float* __restrict__ C,
    int N, int K, float scale,
    long aStride, long bStride, long cStride)
{
    constexpr int BK = 16;
    constexpr int STRD = 20;   // pad: row stride 20 words -> conflict-free LDSM

    __shared__ uint32_t As[2][128][STRD];
    __shared__ uint32_t Bs[2][128][STRD];

    const int bm = blockIdx.y * 128;
    const int bn = blockIdx.x * 128;
    const long bz = blockIdx.z;
    A  += bz * aStride;
    Bm += bz * bStride;
    C  += bz * cStride;

    const int tid  = threadIdx.x;
    const int lane = tid & 31;
    const int wid  = tid >> 5;
    const int wm   = (wid & 1) * 64;   // 2x2 warps, 64x64 warp tile
    const int wn   = (wid >> 1) * 64;
    const int lr   = lane >> 2;
    const int lc   = lane & 3;

    // LDG coords: 128x16 tile = 512 float4 / 128 thr = 4 each (rows +0,32,64,96)
    const int g_row = tid >> 2;        // 0..31
    const int g_kc  = (tid & 3) * 4;

    // ldmatrix per-lane offsets (matrix id mi = lane>>3)
    const int mi = lane >> 3;
    const int aRow = (lane & 7) + (mi & 1) * 8;   // r0..r3 = (m,kk),(m+8,kk),(m,kk+4),(m+8,kk+4)
    const int aCol = (mi >> 1) * 4;
    const int bRow = (lane & 7) + (mi >> 1) * 8;  // r0,r1 = fn b0,b1; r2,r3 = fn+1 b0,b1
    const int bCol = (mi & 1) * 4;

    const uint32_t asb0 = (uint32_t)__cvta_generic_to_shared(&As[0][0][0]);
    const uint32_t bsb0 = (uint32_t)__cvta_generic_to_shared(&Bs[0][0][0]);
    const uint32_t aLane = (uint32_t)((aRow * STRD + aCol) * 4);
    const uint32_t bLane = (uint32_t)((bRow * STRD + bCol) * 4);
    const uint32_t bufBytes = 128 * STRD * 4;

    float acc[4][8][4];
#pragma unroll
    for (int i = 0; i < 4; i++)
#pragma unroll
        for (int j = 0; j < 8; j++)
#pragma unroll
            for (int q = 0; q < 4; q++) acc[i][j][q] = 0.f;

    const int tiles = K / BK;
    float4 ra[4], rb[4];

    auto ldg_tile = [&](int t) {
        const long k0 = (long)t * BK;
#pragma unroll
        for (int i = 0; i < 4; i++) {
            ra[i] = *(const float4*)&A[(long)(bm + g_row + i * 32) * K + k0 + g_kc];
            rb[i] = *(const float4*)&Bm[(long)(bn + g_row + i * 32) * K + k0 + g_kc];
        }
    };

    auto sts_tile = [&](int b) {
#pragma unroll
        for (int i = 0; i < 4; i++) {
            *(uint4*)&As[b][g_row + i * 32][g_kc] =
                make_uint4(f2tf32(ra[i].x), f2tf32(ra[i].y), f2tf32(ra[i].z), f2tf32(ra[i].w));
            *(uint4*)&Bs[b][g_row + i * 32][g_kc] =
                make_uint4(f2tf32(rb[i].x), f2tf32(rb[i].y), f2tf32(rb[i].z), f2tf32(rb[i].w));
        }
    };

    auto compute = [&](int b) {
        const uint32_t asA = asb0 + b * bufBytes + aLane;
        const uint32_t bsB = bsb0 + b * bufBytes + bLane;
#pragma unroll
        for (int kk = 0; kk < BK; kk += 8) {
            uint32_t af[4][4], bf[8][2];
#pragma unroll
            for (int fm = 0; fm < 4; fm++) {
                const int m = wm + fm * 16;
                ldsm4(af[fm][0], af[fm][1], af[fm][2], af[fm][3],
                      asA + (uint32_t)((m * STRD + kk) * 4));
            }
#pragma unroll
            for (int fp = 0; fp < 4; fp++) {
                const int n = wn + fp * 16;
                ldsm4(bf[2 * fp][0], bf[2 * fp][1], bf[2 * fp + 1][0], bf[2 * fp + 1][1],
                      bsB + (uint32_t)((n * STRD + kk) * 4));
            }
#pragma unroll
            for (int fm = 0; fm < 4; fm++)
#pragma unroll
                for (int fn = 0; fn < 8; fn++)
                    mma_tf32(acc[fm][fn], af[fm], bf[fn]);
        }
    };

    // Prologue
    ldg_tile(0);
    sts_tile(0);
    __syncthreads();

    int buf = 0;
    for (int t = 0; t < tiles; t++) {
        const bool has_next = (t + 1 < tiles);
        if (has_next) ldg_tile(t + 1);
        compute(buf);
        if (has_next) {
            __syncthreads();
            sts_tile(buf ^ 1);
            buf ^= 1;
            __syncthreads();
        }
    }

    // Epilogue: c0,c1 at (r, c..c+1); c2,c3 at (r+8, c..c+1)
#pragma unroll
    for (int fm = 0; fm < 4; fm++) {
        const int r = bm + wm + fm * 16 + lr;
        float br0 = 0.f, br1 = 0.f;
        if (BIAS == 2) { br0 = bias[r]; br1 = bias[r + 8]; }
#pragma unroll
        for (int fn = 0; fn < 8; fn++) {
            const int c = bn + wn + fn * 8 + lc * 2;
            float bc0 = 0.f, bc1 = 0.f;
            if (BIAS == 1) { bc0 = bias[c]; bc1 = bias[c + 1]; }
            float2 v0, v1;
            v0.x = acc[fm][fn][0] * scale + bc0 + br0;
            v0.y = acc[fm][fn][1] * scale + bc1 + br0;
            v1.x = acc[fm][fn][2] * scale + bc0 + br1;
            v1.y = acc[fm][fn][3] * scale + bc1 + br1;
            *(float2*)&C[(long)r * N + c] = v0;
            *(float2*)&C[(long)(r + 8) * N + c] = v1;
        }
    }
}

// ---------------------------------------------------------------------------
// Row softmax with mask: one block per (b,q) row of 2048 scores.
// Masked entries contribute nothing and output exact 0 (matches reference).
// ---------------------------------------------------------------------------
__global__ __launch_bounds__(256) void softmax_mask(
    float* __restrict__ S, const int* __restrict__ mask)
{
    const int row = blockIdx.x;
    const int b = row / QN;
    float* sp = S + (long)row * KN;
    const int* mp = mask + (long)b * KN;

    const int tid = threadIdx.x;
    __shared__ float red[32];

    float vals[8];
    int ms[8];
    float lmax = -INFINITY;
#pragma unroll
    for (int i = 0; i < 8; i++) {
        int k = tid + i * 256;
        vals[i] = sp[k];
        ms[i] = mp[k];
        if (ms[i]) lmax = fmaxf(lmax, vals[i]);
    }
#pragma unroll
    for (int o = 16; o > 0; o >>= 1)
        lmax = fmaxf(lmax, __shfl_xor_sync(0xffffffffu, lmax, o));
    if ((tid & 31) == 0) red[tid >> 5] = lmax;
    __syncthreads();
    float rmax = (tid < 8) ? red[tid] : -INFINITY;
#pragma unroll
    for (int o = 4; o > 0; o >>= 1)
        rmax = fmaxf(rmax, __shfl_xor_sync(0xffffffffu, rmax, o));
    if (tid == 0) red[0] = rmax;
    __syncthreads();
    rmax = red[0];

    float lsum = 0.f;
#pragma unroll
    for (int i = 0; i < 8; i++) {
        vals[i] = ms[i] ? __expf(vals[i] - rmax) : 0.f;
        lsum += vals[i];
    }
#pragma unroll
    for (int o = 16; o > 0; o >>= 1)
        lsum += __shfl_xor_sync(0xffffffffu, lsum, o);
    __syncthreads();
    if ((tid & 31) == 0) red[tid >> 5] = lsum;
    __syncthreads();
    float rsum = (tid < 8) ? red[tid] : 0.f;
#pragma unroll
    for (int o = 4; o > 0; o >>= 1)
        rsum += __shfl_xor_sync(0xffffffffu, rsum, o);
    if (tid == 0) red[0] = rsum;
    __syncthreads();
    rsum = red[0];

    float inv = (rsum > 0.f) ? (1.f / rsum) : 0.f;
#pragma unroll
    for (int i = 0; i < 8; i++) {
        int k = tid + i * 256;
        sp[k] = vals[i] * inv;
    }
}

// ---------------------------------------------------------------------------
// kernel_launch
// Inputs: query, key, value, mask, Wq, bq, Wk, bk, Wv, bv
// Output: [ctx (B*QN*DPROJ) | attn (B*QN*KN)]
// ---------------------------------------------------------------------------
extern "C" void kernel_launch(void* const* d_in, const int* in_sizes, int n_in,
                              void* d_out, int out_size)
{
    const float* query = (const float*)d_in[0];
    const float* key   = (const float*)d_in[1];
    const float* value = (const float*)d_in[2];
    const int*   mask  = (const int*)d_in[3];
    const float* Wq    = (const float*)d_in[4];
    const float* bq    = (const float*)d_in[5];
    const float* Wk    = (const float*)d_in[6];
    const float* bk    = (const float*)d_in[7];
    const float* Wv    = (const float*)d_in[8];
    const float* bv    = (const float*)d_in[9];

    float* ctx  = (float*)d_out;
    float* attn = (float*)d_out + (size_t)BATCH * QN * DPROJ;

    float *pq, *pk, *pvT;
    cudaGetSymbolAddress((void**)&pq, g_pq);
    cudaGetSymbolAddress((void**)&pk, g_pk);
    cudaGetSymbolAddress((void**)&pvT, g_pvT);

    dim3 blk(128);

    // Q/K projections: C[token, d] = query @ Wq^T + bq   (col-bias)
    {
        dim3 grid(DPROJ / 128, (BATCH * QN) / 128, 1);
        gemm_tc<1><<<grid, blk>>>(query, Wq, bq, pq, DPROJ, DIN, 1.f, 0, 0, 0);
        gemm_tc<1><<<grid, blk>>>(key,   Wk, bk, pk, DPROJ, DIN, 1.f, 0, 0, 0);
    }

    // V projection TRANSPOSED: pvT[d, token] = Wv @ value^T + bv[d]  (row-bias)
    {
        dim3 grid(KN / 128, DPROJ / 128, BATCH);
        gemm_tc<2><<<grid, blk>>>(Wv, value, bv, pvT, KN, DIN, 1.f,
                                  0, (long)KN * DIN, (long)DPROJ * KN);
    }

    // Scores: [QN, DPROJ] x [KN, DPROJ]^T * (1/32) -> attn region
    {
        dim3 grid(KN / 128, QN / 128, BATCH);
        gemm_tc<0><<<grid, blk>>>(pq, pk, nullptr, attn, KN, DPROJ,
                                  0.03125f,
                                  (long)QN * DPROJ, (long)KN * DPROJ, (long)QN * KN);
    }

    // Masked softmax in-place over attn rows
    softmax_mask<<<BATCH * QN, 256>>>(attn, mask);

    // ctx[q, d] = sum_k attn[q,k] * pvT[d,k]   (NT)
    {
        dim3 grid(DPROJ / 128, QN / 128, BATCH);
        gemm_tc<0><<<grid, blk>>>(attn, pvT, nullptr, ctx, DPROJ, KN,
                                  1.f,
                                  (long)QN * KN, (long)DPROJ * KN, (long)QN * DPROJ);
    }
}